// round 9
// baseline (speedup 1.0000x reference)
#include <cuda_runtime.h>
#include <cstdint>

#define CCH 32
#define DD 48
#define HHH 48
#define WWW 48
#define HW (HHH*WWW)           // 2304
#define DHW (DD*HHH*WWW)       // 110592
#define EPSf 1e-6f
#define THREADS 128

// Pre-transposed mix weights: g_WT[m*32 + o] = w_mix[o*256 + m]
__device__ float g_WT[256 * 32];

__global__ void prep_WT_kernel(const float* __restrict__ w_mix) {
    int i = blockIdx.x * 256 + threadIdx.x;
    if (i < 256 * 32) {
        int m = i >> 5, o = i & 31;
        g_WT[m * 32 + o] = w_mix[o * 256 + m];
    }
}

// packed fp32x2 helpers
__device__ __forceinline__ void ffma2(unsigned long long &acc, unsigned long long w, unsigned long long v) {
    asm("fma.rn.f32x2 %0, %1, %2, %0;" : "+l"(acc) : "l"(w), "l"(v));
}
__device__ __forceinline__ unsigned long long pack2(float a) {
    unsigned long long r; asm("mov.b64 %0, {%1, %1};" : "=l"(r) : "f"(a)); return r;
}
__device__ __forceinline__ float2 unpack2(unsigned long long a) {
    float2 f; asm("mov.b64 {%0, %1}, %2;" : "=f"(f.x), "=f"(f.y) : "l"(a)); return f;
}

__device__ __forceinline__ float reflectf(float t, float size) {
    float c = fabsf(t + 0.5f);
    float m = fmodf(c, 2.0f * size);
    return fminf(m, 2.0f * size - m) - 0.5f;
}

// Dynamic shared layout (all 16B aligned):
//   [0)        s_WT   256*32 floats  (32 KB)
//   [32768)    s_S    2*16*128 floats (16 KB)  token stage, double buffered
//   [49152)    s_wf   12*32 floats
//   [50688)    s_bf   16 floats
//   [50752)    s_bmix 32 floats
//   [50880)    s_sg   8 floats
#define OFF_WT   0
#define OFF_S    32768
#define OFF_WF   49152
#define OFF_BF   50688
#define OFF_BMIX 50752
#define OFF_SG   50880
#define SMEM_DYN 50944

__global__ __launch_bounds__(THREADS)
void geo_sample3d_kernel(const float* __restrict__ x,
                         const float* __restrict__ w_field,
                         const float* __restrict__ b_field,
                         const float* __restrict__ gates,
                         const float* __restrict__ b_mix,
                         float* __restrict__ out,
                         int total_vox)
{
    extern __shared__ __align__(16) char dsm[];
    float* s_WT   = (float*)(dsm + OFF_WT);
    float* s_Sb   = (float*)(dsm + OFF_S);
    float* s_wf   = (float*)(dsm + OFF_WF);
    float* s_bf   = (float*)(dsm + OFF_BF);
    float* s_bmix = (float*)(dsm + OFF_BMIX);
    float* s_sg   = (float*)(dsm + OFF_SG);

    const int tid = threadIdx.x;

    #pragma unroll 4
    for (int i = tid; i < 256 * 32; i += THREADS) s_WT[i] = g_WT[i];
    for (int i = tid; i < 12 * CCH; i += THREADS) s_wf[i] = w_field[i];
    if (tid < 12)  s_bf[tid]   = b_field[tid];
    if (tid < CCH) s_bmix[tid] = b_mix[tid];
    if (tid < 8)   s_sg[tid]   = 1.0f / (1.0f + expf(-gates[tid]));
    __syncthreads();

    const int vb0 = blockIdx.x * THREADS;
    const int idx = vb0 + tid;                 // total_vox is a multiple of THREADS

    const int n   = idx / DHW;
    const int zyx = idx - n * DHW;
    const int z   = zyx / HW;
    const int r2i = zyx - z * HW;
    const int y   = r2i / WWW;
    const int w   = r2i - y * WWW;

    const float* __restrict__ xn = x + (size_t)n * CCH * DHW;

    // ---- Phase 1: field conv f[12] ----
    float f[12];
    #pragma unroll
    for (int o = 0; o < 12; o++) f[o] = s_bf[o];
    #pragma unroll 4
    for (int c = 0; c < CCH; c++) {
        float xc = xn[c * DHW + zyx];
        #pragma unroll
        for (int o = 0; o < 12; o++) f[o] = fmaf(s_wf[o * CCH + c], xc, f[o]);
    }

    // ---- Phase 2: geometry + folded token coefficients ----
    int   ib[6], ox[6], oy[6], oz[6];
    float fx[6], fy[6], fz[6];
    float cA[3], cG[9], cLs[3];
    float sumIr2 = 0.0f;

    const float gx0 = (w + 0.5f) * (2.0f / WWW) - 1.0f;
    const float gy0 = (y + 0.5f) * (2.0f / HHH) - 1.0f;
    const float gz0 = (z + 0.5f) * (2.0f / DD)  - 1.0f;

    #pragma unroll
    for (int k = 0; k < 3; k++) {
        float vx = f[4*k+0], vy = f[4*k+1], vz = f[4*k+2], fr = f[4*k+3];
        float inv_norm = rsqrtf(vx*vx + vy*vy + vz*vz + EPSf);
        float ux = vx * inv_norm, uy = vy * inv_norm, uz = vz * inv_norm;
        float r  = 0.5f + 1.5f / (1.0f + expf(-fr));
        float dx = 2.0f * r * ux / ((float)WWW + EPSf);
        float dy = 2.0f * r * uy / ((float)HHH + EPSf);
        float dz = 2.0f * r * uz / ((float)DD  + EPSf);
        float invr = 1.0f / (r + EPSf);
        float ir2  = invr * invr;
        sumIr2 += ir2;

        cA[k]     = 0.5f * s_sg[1+k];
        cG[0*3+k] = s_sg[4] * 0.5f * invr * ux;
        cG[1*3+k] = s_sg[5] * 0.5f * invr * uy;
        cG[2*3+k] = s_sg[6] * 0.5f * invr * uz;
        cLs[k]    = s_sg[7] * (1.0f/3.0f) * ir2;

        #pragma unroll
        for (int s2 = 0; s2 < 2; s2++) {
            float sgn = s2 ? -1.0f : 1.0f;
            int   si  = 2*k + s2;
            float txu = ((gx0 + sgn*dx + 1.0f) * (float)WWW - 1.0f) * 0.5f;
            float tyu = ((gy0 + sgn*dy + 1.0f) * (float)HHH - 1.0f) * 0.5f;
            float tzu = ((gz0 + sgn*dz + 1.0f) * (float)DD  - 1.0f) * 0.5f;
            float ixs = reflectf(txu, (float)WWW);
            float iys = reflectf(tyu, (float)HHH);
            float izs = reflectf(tzu, (float)DD);

            float x0f = floorf(ixs), y0f = floorf(iys), z0f = floorf(izs);
            fx[si] = ixs - x0f;  fy[si] = iys - y0f;  fz[si] = izs - z0f;

            int x0i = (int)x0f; x0i = max(0, min(x0i, WWW-1)); int x1i = min(x0i+1, WWW-1);
            int y0i = (int)y0f; y0i = max(0, min(y0i, HHH-1)); int y1i = min(y0i+1, HHH-1);
            int z0i = (int)z0f; z0i = max(0, min(z0i, DD-1));  int z1i = min(z0i+1, DD-1);

            ib[si] = z0i * HW + y0i * WWW + x0i;
            ox[si] = x1i - x0i;
            oy[si] = (y1i - y0i) * WWW;
            oz[si] = (z1i - z0i) * HW;
        }
    }

    const float cLx = -s_sg[7] * (2.0f/3.0f) * sumIr2;
    const float cx  = s_sg[0];

    // ---- Phase 3: per channel-pair: gather tokens -> stage -> block GEMM ----
    const int voxg = tid >> 2;   // 4-voxel group
    const int outg = tid & 3;    // 8-output group

    unsigned long long acc[16];
    #pragma unroll
    for (int j = 0; j < 16; j++) acc[j] = 0ull;

    #pragma unroll 1
    for (int p = 0; p < 16; p++) {
        float tv[16];
        #pragma unroll
        for (int half = 0; half < 2; half++) {
            const int c = 2*p + half;
            const float* __restrict__ bc = xn + c * DHW;
            float xc = bc[zyx];

            float sv[6];
            #pragma unroll
            for (int si = 0; si < 6; si++) {
                const float* pp = bc + ib[si];
                const float* pz = pp + oz[si];
                float v000 = pp[0],       v001 = pp[ox[si]];
                float v010 = pp[oy[si]],  v011 = pp[oy[si] + ox[si]];
                float v100 = pz[0],       v101 = pz[ox[si]];
                float v110 = pz[oy[si]],  v111 = pz[oy[si] + ox[si]];
                float c00 = v000 + fx[si] * (v001 - v000);
                float c01 = v010 + fx[si] * (v011 - v010);
                float c10 = v100 + fx[si] * (v101 - v100);
                float c11 = v110 + fx[si] * (v111 - v110);
                float c0  = c00 + fy[si] * (c01 - c00);
                float c1  = c10 + fy[si] * (c11 - c10);
                sv[si] = c0 + fz[si] * (c1 - c0);
            }

            float s0 = sv[0] + sv[1], m0 = sv[0] - sv[1];
            float s1 = sv[2] + sv[3], m1 = sv[2] - sv[3];
            float s2 = sv[4] + sv[5], m2 = sv[4] - sv[5];

            tv[0*2+half] = cx * xc;
            tv[1*2+half] = cA[0] * s0;
            tv[2*2+half] = cA[1] * s1;
            tv[3*2+half] = cA[2] * s2;
            tv[4*2+half] = cG[0]*m0 + cG[1]*m1 + cG[2]*m2;
            tv[5*2+half] = cG[3]*m0 + cG[4]*m1 + cG[5]*m2;
            tv[6*2+half] = cG[6]*m0 + cG[7]*m1 + cG[8]*m2;
            tv[7*2+half] = cLs[0]*s0 + cLs[1]*s1 + cLs[2]*s2 + cLx * xc;
        }

        // double-buffered stage: barrier at iter p-1 already ordered the
        // consume of buffer (p&1) from iter p-2 before this write.
        float* s_S = s_Sb + (p & 1) * (16 * 128);
        #pragma unroll
        for (int s = 0; s < 16; s++) s_S[s * 128 + tid] = tv[s];
        __syncthreads();

        #pragma unroll
        for (int s = 0; s < 16; s++) {
            const int t    = s >> 1;
            const int half = s & 1;
            const int m    = t * 32 + 2*p + half;
            const float4* wr4 = (const float4*)(s_WT + m * 32) + outg * 2;
            float4 w0 = wr4[0];
            float4 w1 = wr4[1];
            unsigned long long q00, q01, q10, q11;
            asm("mov.b64 %0, {%1, %2};" : "=l"(q00) : "f"(w0.x), "f"(w0.y));
            asm("mov.b64 %0, {%1, %2};" : "=l"(q01) : "f"(w0.z), "f"(w0.w));
            asm("mov.b64 %0, {%1, %2};" : "=l"(q10) : "f"(w1.x), "f"(w1.y));
            asm("mov.b64 %0, {%1, %2};" : "=l"(q11) : "f"(w1.z), "f"(w1.w));
            const float4 av = *((const float4*)(s_S + s * 128) + voxg);
            unsigned long long a0 = pack2(av.x), a1 = pack2(av.y),
                               a2 = pack2(av.z), a3 = pack2(av.w);
            ffma2(acc[0],  q00, a0); ffma2(acc[1],  q01, a0);
            ffma2(acc[2],  q10, a0); ffma2(acc[3],  q11, a0);
            ffma2(acc[4],  q00, a1); ffma2(acc[5],  q01, a1);
            ffma2(acc[6],  q10, a1); ffma2(acc[7],  q11, a1);
            ffma2(acc[8],  q00, a2); ffma2(acc[9],  q01, a2);
            ffma2(acc[10], q10, a2); ffma2(acc[11], q11, a2);
            ffma2(acc[12], q00, a3); ffma2(acc[13], q01, a3);
            ffma2(acc[14], q10, a3); ffma2(acc[15], q11, a3);
        }
    }

    // ---- Phase 4: epilogue — float4 over 4 consecutive voxels ----
    const int vtile = vb0 + voxg * 4;
    {
        const int n2    = vtile / DHW;
        const int zyx2  = vtile - n2 * DHW;
        const float* __restrict__ xn2 = x + (size_t)n2 * CCH * DHW;
        float* __restrict__ on2       = out + (size_t)n2 * CCH * DHW;
        #pragma unroll
        for (int jj = 0; jj < 4; jj++) {
            int o0 = outg * 8 + 2*jj;
            float2 d0 = unpack2(acc[0*4 + jj]);
            float2 d1 = unpack2(acc[1*4 + jj]);
            float2 d2 = unpack2(acc[2*4 + jj]);
            float2 d3 = unpack2(acc[3*4 + jj]);
            {
                float4 xv = *(const float4*)(xn2 + (size_t)o0 * DHW + zyx2);
                float b = s_bmix[o0];
                float4 ov = make_float4(xv.x + d0.x + b, xv.y + d1.x + b,
                                        xv.z + d2.x + b, xv.w + d3.x + b);
                *(float4*)(on2 + (size_t)o0 * DHW + zyx2) = ov;
            }
            {
                int o1 = o0 + 1;
                float4 xv = *(const float4*)(xn2 + (size_t)o1 * DHW + zyx2);
                float b = s_bmix[o1];
                float4 ov = make_float4(xv.x + d0.y + b, xv.y + d1.y + b,
                                        xv.z + d2.y + b, xv.w + d3.y + b);
                *(float4*)(on2 + (size_t)o1 * DHW + zyx2) = ov;
            }
        }
    }
}

extern "C" void kernel_launch(void* const* d_in, const int* in_sizes, int n_in,
                              void* d_out, int out_size)
{
    const float* x       = (const float*)d_in[0];
    const float* w_field = (const float*)d_in[1];
    const float* b_field = (const float*)d_in[2];
    const float* gates   = (const float*)d_in[3];
    const float* w_mix   = (const float*)d_in[4];
    const float* b_mix   = (const float*)d_in[5];
    float* out = (float*)d_out;

    (void)cudaFuncSetAttribute(geo_sample3d_kernel,
                               cudaFuncAttributeMaxDynamicSharedMemorySize, SMEM_DYN);

    prep_WT_kernel<<<32, 256>>>(w_mix);

    int total_vox = in_sizes[0] / CCH;                    // 221184
    int blocks = (total_vox + THREADS - 1) / THREADS;     // 1728
    geo_sample3d_kernel<<<blocks, THREADS, SMEM_DYN>>>(x, w_field, b_field, gates,
                                                       b_mix, out, total_vox);
}